// round 8
// baseline (speedup 1.0000x reference)
#include <cuda_runtime.h>
#include <cstdint>

#define BB 64
#define CC 4096
#define IND 512
#define OO 16
#define TI 16                 // i-tile
#define NTILES (IND / TI)     // 32
#define NCAPW 2               // capsules per WARP
#define WARPS 4               // warps per CTA (one per SMSP!)
#define NTH (32 * WARPS)
#define CAPS_CTA (NCAPW * WARPS)   // 8
#define PIPE 2

#define XCAP 1024             // 64 rows x 16 words per capsule per stage
#define WCAP 256              // 16 rows x 16 words per capsule per stage
#define XWARP (NCAPW * XCAP)  // 2048 floats
#define WWARP (NCAPW * WCAP)  // 512 floats
#define XSEG (PIPE * WARPS * XWARP)           // 16384 floats
#define SMEM_FLOATS (XSEG + PIPE * WARPS * WWARP)   // 20480 floats = 80 KB

// chunk swizzle: logical 16B chunk j of row r lives at position sigma(r,j)
__device__ __forceinline__ int sig(int r, int j) {
    return (j + ((r >> 1) & 3)) & 3;
}

// ---- packed f32x2 helpers ----
__device__ __forceinline__ uint64_t pack_dup(float x) {
    uint64_t r;
    asm("mov.b64 %0, {%1, %1};" : "=l"(r) : "f"(x));
    return r;
}
__device__ __forceinline__ void fma2(uint64_t& d, uint64_t a, uint64_t b) {
    asm("fma.rn.f32x2 %0, %1, %2, %0;" : "+l"(d) : "l"(a), "l"(b));
}
__device__ __forceinline__ void unpack2(uint64_t v, float& lo, float& hi) {
    asm("mov.b64 {%0, %1}, %2;" : "=f"(lo), "=f"(hi) : "l"(v));
}

// ---- cp.async 16B, L1-bypass ----
__device__ __forceinline__ void cp16(void* dst_smem, const void* src) {
    uint32_t d = (uint32_t)__cvta_generic_to_shared(dst_smem);
    asm volatile("cp.async.cg.shared.global [%0], [%1], 16;"
                 :: "r"(d), "l"(src) : "memory");
}
__device__ __forceinline__ void cp_commit() {
    asm volatile("cp.async.commit_group;" ::: "memory");
}
__device__ __forceinline__ void cp_wait1() {
    asm volatile("cp.async.wait_group 1;" ::: "memory");
}
__device__ __forceinline__ void cp_wait0() {
    asm volatile("cp.async.wait_group 0;" ::: "memory");
}

extern __shared__ float sm[];

__global__ __launch_bounds__(NTH)
void primarycaps_kernel(const float* __restrict__ x,
                        const float* __restrict__ W,
                        const float* __restrict__ bias,
                        float* __restrict__ out)
{
    const int t    = threadIdx.x;
    const int wid  = t >> 5;          // warp -> SMSP (0..3)
    const int lane = t & 31;

    const int c0 = blockIdx.x * CAPS_CTA + wid * NCAPW;   // this warp's 2 caps

    // compute map (within warp)
    const int tb  = lane & 7;         // b-group: owns b = tb + 8k
    const int to  = (lane >> 3) & 1;  // o-half
    const int cap = lane >> 4;        // capsule within warp

    // staging map: lane -> (row base, 16B chunk); one instr = 8 rows x 64B
    const int sr = (lane >> 2) & 7;
    const int sj = lane & 3;

    // per-warp smem bases
    float* const sX0 = sm + (0 * WARPS + wid) * XWARP;
    float* const sX1 = sm + (1 * WARPS + wid) * XWARP;
    float* const sW0 = sm + XSEG + (0 * WARPS + wid) * WWARP;
    float* const sW1 = sm + XSEG + (1 * WARPS + wid) * WWARP;

    // ---- accumulators: 8 b-rows x 4 o-pairs (packed f32x2) ----
    uint64_t acc[8][4];
    #pragma unroll
    for (int k = 0; k < 8; ++k)
        #pragma unroll
        for (int j = 0; j < 4; ++j)
            acc[k][j] = 0ULL;

    // ---- stage helper: tile jt into buffer bf (this warp only) ----
    auto stage = [&](int bf, int jt) {
        float* dx = bf ? sX1 : sX0;
        #pragma unroll
        for (int cc = 0; cc < NCAPW; ++cc) {
            #pragma unroll
            for (int k = 0; k < 8; ++k) {
                const int row = sr + 8 * k;
                cp16(&dx[cc * XCAP + row * 16 + sig(row, sj) * 4],
                     x + ((size_t)row * CC + c0 + cc) * IND
                       + (size_t)jt * TI + sj * 4);
            }
        }
        float* dw = bf ? sW1 : sW0;
        #pragma unroll
        for (int cc = 0; cc < NCAPW; ++cc) {
            #pragma unroll
            for (int m = 0; m < 2; ++m) {
                const int i = sr + 8 * m;
                cp16(&dw[cc * WCAP + i * 16 + sig(i, sj) * 4],
                     W + (((size_t)(c0 + cc)) * IND + (size_t)jt * TI + i) * OO
                       + sj * 4);
            }
        }
        cp_commit();
    };

    // ---- prologue ----
    stage(0, 0);

    for (int j = 0; j < NTILES; ++j) {
        // issue next stage first (overlap), then wait for tile j
        if (j + 1 < NTILES) {
            stage((j + 1) & 1, j + 1);
            cp_wait1();
        } else {
            cp_wait0();
        }
        __syncwarp();

        // ---- compute tile j ----
        const float* __restrict__ xb = (j & 1) ? sX1 : sX0;
        const float* __restrict__ wb = (j & 1) ? sW1 : sW0;
        xb += cap * XCAP;
        wb += cap * WCAP;

        #pragma unroll
        for (int q = 0; q < 4; ++q) {           // 4-i blocks
            float4 xv[8];
            #pragma unroll
            for (int k = 0; k < 8; ++k) {
                const int row = tb + 8 * k;
                xv[k] = *(const float4*)&xb[row * 16 + sig(row, q) * 4];
            }

            #pragma unroll
            for (int r = 0; r < 4; ++r) {
                const int i = q * 4 + r;
                const ulonglong2 wA =
                    *(const ulonglong2*)&wb[i * 16 + sig(i, 2 * to) * 4];
                const ulonglong2 wB =
                    *(const ulonglong2*)&wb[i * 16 + sig(i, 2 * to + 1) * 4];

                #pragma unroll
                for (int k = 0; k < 8; ++k) {
                    const float xs = (r == 0) ? xv[k].x :
                                     (r == 1) ? xv[k].y :
                                     (r == 2) ? xv[k].z : xv[k].w;
                    const uint64_t xd = pack_dup(xs);
                    fma2(acc[k][0], xd, wA.x);
                    fma2(acc[k][1], xd, wA.y);
                    fma2(acc[k][2], xd, wB.x);
                    fma2(acc[k][3], xd, wB.y);
                }
            }
        }
        __syncwarp();   // warp done reading buffer before it is refilled
    }

    // ---- epilogue ----
    const int c  = c0 + cap;
    const int o0 = to * 8;
    const float4* bias4 = (const float4*)(bias + (size_t)c * OO + o0);
    const float4 bz0 = bias4[0];
    const float4 bz1 = bias4[1];

    #pragma unroll
    for (int k = 0; k < 8; ++k) {
        float v0, v1, v2, v3, v4, v5, v6, v7;
        unpack2(acc[k][0], v0, v1);
        unpack2(acc[k][1], v2, v3);
        unpack2(acc[k][2], v4, v5);
        unpack2(acc[k][3], v6, v7);

        float4 lo = make_float4(v0 + bz0.x, v1 + bz0.y, v2 + bz0.z, v3 + bz0.w);
        float4 hi = make_float4(v4 + bz1.x, v5 + bz1.y, v6 + bz1.z, v7 + bz1.w);

        const int b = tb + 8 * k;
        float* op = out + ((size_t)b * CC + c) * OO + o0;
        *(float4*)(op)     = lo;
        *(float4*)(op + 4) = hi;
    }
}

extern "C" void kernel_launch(void* const* d_in, const int* in_sizes, int n_in,
                              void* d_out, int out_size)
{
    (void)in_sizes; (void)n_in; (void)out_size;
    const float* x    = (const float*)d_in[0];
    const float* W    = (const float*)d_in[1];
    const float* bias = (const float*)d_in[2];
    float*       out  = (float*)d_out;

    const int smem_bytes = SMEM_FLOATS * sizeof(float);   // 80 KB
    static bool attr_done = false;
    if (!attr_done) {
        cudaFuncSetAttribute(primarycaps_kernel,
                             cudaFuncAttributeMaxDynamicSharedMemorySize,
                             smem_bytes);
        attr_done = true;
    }
    primarycaps_kernel<<<CC / CAPS_CTA, NTH, smem_bytes>>>(x, W, bias, out);
}